// round 4
// baseline (speedup 1.0000x reference)
#include <cuda_runtime.h>

// ---------------------------------------------------------------------------
// GCNModelVAE forward on GB300 (fp32, f32x2 packed-FMA SIMT GEMMs)
//   support = x @ W_hidden                    [8192,512]@[512,256]
//   hidden  = relu(adj @ support)             [8192,8192]@[8192,256]  (split-K 2)
//   s       = hidden @ [W_mean | W_logstd]    [8192,256]@[256,128]
//   zcat    = adj @ s                         [8192,8192]@[8192,128]  (split-K 4)
//   z_mean = zcat[:, :64]; z_log_std = zcat[:, 64:]
//   recon   = z_mean @ z_mean.T               symmetric, upper CTAs only
// Output layout: [recon (8192*8192) | z_mean (8192*64) | z_log_std (8192*64)]
// ---------------------------------------------------------------------------

#define NN   8192
#define DIN  512
#define DHID 256
#define DZ   64
#define DCAT 128

typedef unsigned long long u64;

// ---- scratch (no allocations allowed: one big __device__ array) ----
#define OFF_SUPPORT 0                              // NN*DHID = 2,097,152
#define OFF_HIDDEN  (2*1024*1024 + 49152)          // 2,146,304 (keep 16B aligned)
#define OFF_PART    (2*OFF_HIDDEN)                 // plenty of headroom below
// simpler explicit offsets:
#undef OFF_HIDDEN
#undef OFF_PART
#define SZ_SUPPORT (NN*DHID)          // 2,097,152
#define SZ_HIDDEN  (NN*DHID)          // 2,097,152
#define SZ_PART    (2*NN*DHID)        // 4,194,304  (reused: 2x[NN*DHID] or 4x[NN*DCAT])
#define SZ_WCAT    (DHID*DCAT)        // 32,768
#define SZ_S       (NN*DCAT)          // 1,048,576
#define SZ_ZCAT    (NN*DCAT)          // 1,048,576
#define OFF_SUPPORT 0
#define OFF_HIDDEN  (OFF_SUPPORT + SZ_SUPPORT)
#define OFF_PART    (OFF_HIDDEN  + SZ_HIDDEN)
#define OFF_WCAT    (OFF_PART    + SZ_PART)
#define OFF_S       (OFF_WCAT    + SZ_WCAT)
#define OFF_ZCAT    (OFF_S       + SZ_S)
#define SZ_TOTAL    (OFF_ZCAT    + SZ_ZCAT)

__device__ __align__(16) float g_scratch[SZ_TOTAL];

// ---- f32x2 helpers (Blackwell packed fp32: 2 FMAs per instruction) ----
__device__ __forceinline__ void ffma2(u64& d, u64 a, u64 b) {
    asm("fma.rn.f32x2 %0, %1, %2, %0;" : "+l"(d) : "l"(a), "l"(b));
}
__device__ __forceinline__ u64 pack2(float lo, float hi) {
    u64 r; asm("mov.b64 %0, {%1, %2};" : "=l"(r) : "f"(lo), "f"(hi)); return r;
}
__device__ __forceinline__ float2 unpack2(u64 v) {
    float2 r; asm("mov.b64 {%0, %1}, %2;" : "=f"(r.x), "=f"(r.y) : "l"(v)); return r;
}

// ---- shared inner micro-kernel: 8 k-steps, 8x8 per thread, f32x2 ----
__device__ __forceinline__ void mm_inner(const float (*As)[128], const float (*Bs)[128],
                                         u64 acc[8][4], int tm, int tn) {
#pragma unroll
    for (int k = 0; k < 8; k++) {
        float4 a0 = *(const float4*)&As[k][tm * 8];
        float4 a1 = *(const float4*)&As[k][tm * 8 + 4];
        float4 b0 = *(const float4*)&Bs[k][tn * 8];
        float4 b1 = *(const float4*)&Bs[k][tn * 8 + 4];
        u64 bp0 = pack2(b0.x, b0.y);
        u64 bp1 = pack2(b0.z, b0.w);
        u64 bp2 = pack2(b1.x, b1.y);
        u64 bp3 = pack2(b1.z, b1.w);
        float a_s[8] = {a0.x, a0.y, a0.z, a0.w, a1.x, a1.y, a1.z, a1.w};
#pragma unroll
        for (int i = 0; i < 8; i++) {
            u64 ai = pack2(a_s[i], a_s[i]);
            ffma2(acc[i][0], ai, bp0);
            ffma2(acc[i][1], ai, bp1);
            ffma2(acc[i][2], ai, bp2);
            ffma2(acc[i][3], ai, bp3);
        }
    }
}

// ---------------------------------------------------------------------------
// Generic GEMM: C[M,N] (+= over split-K slices) = A[M,K] @ B[K,N], row-major.
// BM=BN=128, BK=8, 256 threads, 8x8 micro-tile. blockIdx.z = split-K slice;
// slice z writes its partial into C + z*M*N. Requires M%128==0, N%128==0,
// kChunk%8==0, K == gridDim.z*kChunk.
// ---------------------------------------------------------------------------
__global__ __launch_bounds__(256, 2)
void gemm128(const float* __restrict__ A, const float* __restrict__ B,
             float* __restrict__ C, int M, int N, int K, int kChunk) {
    __shared__ float As[8][128];
    __shared__ float Bs[8][128];

    const int tid = threadIdx.x;
    const int tm = tid >> 4;          // 0..15
    const int tn = tid & 15;          // 0..15
    const int m0 = blockIdx.y * 128;
    const int n0 = blockIdx.x * 128;
    const int kBegin = blockIdx.z * kChunk;
    const int kEnd = kBegin + kChunk;
    float* Cout = C + (size_t)blockIdx.z * (size_t)M * (size_t)N;

    u64 acc[8][4];
#pragma unroll
    for (int i = 0; i < 8; i++)
#pragma unroll
        for (int j = 0; j < 4; j++) acc[i][j] = 0ull;

    // A tile loader: 128 rows x 8 cols, transpose-scatter into As[k][m]
    const int arow = tid >> 1;            // 0..127
    const int akb = (tid & 1) * 4;        // 0 or 4
    // B tile loader: 8 rows x 128 cols, direct into Bs[k][n]
    const int bkr = tid >> 5;             // 0..7
    const int bc4 = (tid & 31) * 4;       // 0..124

    const float* Aptr = A + (size_t)(m0 + arow) * (size_t)K + akb;
    const float* Bptr = B + (size_t)bkr * (size_t)N + n0 + bc4;

    float4 av = *(const float4*)(Aptr + kBegin);
    float4 bv = *(const float4*)(Bptr + (size_t)kBegin * (size_t)N);

    for (int k0 = kBegin; k0 < kEnd; k0 += 8) {
        As[akb + 0][arow] = av.x;
        As[akb + 1][arow] = av.y;
        As[akb + 2][arow] = av.z;
        As[akb + 3][arow] = av.w;
        *(float4*)&Bs[bkr][bc4] = bv;
        __syncthreads();

        const int k1 = k0 + 8;
        if (k1 < kEnd) {
            av = *(const float4*)(Aptr + k1);
            bv = *(const float4*)(Bptr + (size_t)k1 * (size_t)N);
        }

        mm_inner(As, Bs, acc, tm, tn);
        __syncthreads();
    }

    // epilogue
    float* Crow = Cout + (size_t)(m0 + tm * 8) * (size_t)N + n0 + tn * 8;
#pragma unroll
    for (int i = 0; i < 8; i++) {
        float2 v0 = unpack2(acc[i][0]);
        float2 v1 = unpack2(acc[i][1]);
        float2 v2 = unpack2(acc[i][2]);
        float2 v3 = unpack2(acc[i][3]);
        float4 o0 = make_float4(v0.x, v0.y, v1.x, v1.y);
        float4 o1 = make_float4(v2.x, v2.y, v3.x, v3.y);
        *(float4*)(Crow + (size_t)i * (size_t)N) = o0;
        *(float4*)(Crow + (size_t)i * (size_t)N + 4) = o1;
    }
}

// ---------------------------------------------------------------------------
// Symmetric rank-K: recon = Z @ Z^T, Z:[NN, DZ]. Only bj>=bi CTAs compute;
// off-diagonal tiles are mirrored into the lower triangle.
// ---------------------------------------------------------------------------
__global__ __launch_bounds__(256, 2)
void recon_syrk(const float* __restrict__ Z, float* __restrict__ C) {
    const int bi = blockIdx.y, bj = blockIdx.x;
    if (bj < bi) return;

    __shared__ float As[8][128];
    __shared__ float Bs[8][128];

    const int tid = threadIdx.x;
    const int tm = tid >> 4;
    const int tn = tid & 15;
    const int m0 = bi * 128;
    const int n0 = bj * 128;
    const int row = tid >> 1;
    const int kb = (tid & 1) * 4;

    u64 acc[8][4];
#pragma unroll
    for (int i = 0; i < 8; i++)
#pragma unroll
        for (int j = 0; j < 4; j++) acc[i][j] = 0ull;

    const float* Ap = Z + (size_t)(m0 + row) * DZ + kb;
    const float* Bp = Z + (size_t)(n0 + row) * DZ + kb;
    float4 av = *(const float4*)Ap;
    float4 bv = *(const float4*)Bp;

    for (int k0 = 0; k0 < DZ; k0 += 8) {
        As[kb + 0][row] = av.x; As[kb + 1][row] = av.y;
        As[kb + 2][row] = av.z; As[kb + 3][row] = av.w;
        Bs[kb + 0][row] = bv.x; Bs[kb + 1][row] = bv.y;
        Bs[kb + 2][row] = bv.z; Bs[kb + 3][row] = bv.w;
        __syncthreads();

        const int k1 = k0 + 8;
        if (k1 < DZ) {
            av = *(const float4*)(Ap + k1);
            bv = *(const float4*)(Bp + k1);
        }

        mm_inner(As, Bs, acc, tm, tn);
        __syncthreads();
    }

    const size_t ldc = NN;
#pragma unroll
    for (int i = 0; i < 8; i++) {
        float v[8];
        float2 t;
        t = unpack2(acc[i][0]); v[0] = t.x; v[1] = t.y;
        t = unpack2(acc[i][1]); v[2] = t.x; v[3] = t.y;
        t = unpack2(acc[i][2]); v[4] = t.x; v[5] = t.y;
        t = unpack2(acc[i][3]); v[6] = t.x; v[7] = t.y;
        const size_t r = (size_t)(m0 + tm * 8 + i);
        const size_t c = (size_t)(n0 + tn * 8);
        float4 o0 = make_float4(v[0], v[1], v[2], v[3]);
        float4 o1 = make_float4(v[4], v[5], v[6], v[7]);
        *(float4*)&C[r * ldc + c] = o0;
        *(float4*)&C[r * ldc + c + 4] = o1;
        if (bi != bj) {
#pragma unroll
            for (int j = 0; j < 8; j++) C[(c + j) * ldc + r] = v[j];
        }
    }
}

// ---- small helper kernels ----
__global__ void pack_w(const float* __restrict__ Wm, const float* __restrict__ Wl,
                       float* __restrict__ Wcat) {
    int i = blockIdx.x * blockDim.x + threadIdx.x;   // DHID*DCAT = 32768
    if (i >= DHID * DCAT) return;
    int r = i >> 7, c = i & 127;
    Wcat[i] = (c < DZ) ? Wm[r * DZ + c] : Wl[r * DZ + (c - DZ)];
}

__global__ void reduce2_relu(const float* __restrict__ p0, const float* __restrict__ p1,
                             float* __restrict__ out, int n4) {
    int i = blockIdx.x * blockDim.x + threadIdx.x;
    if (i >= n4) return;
    float4 a = ((const float4*)p0)[i];
    float4 b = ((const float4*)p1)[i];
    float4 r;
    r.x = fmaxf(a.x + b.x, 0.f);
    r.y = fmaxf(a.y + b.y, 0.f);
    r.z = fmaxf(a.z + b.z, 0.f);
    r.w = fmaxf(a.w + b.w, 0.f);
    ((float4*)out)[i] = r;
}

__global__ void reduce4(const float* __restrict__ p, float* __restrict__ out,
                        int n4, size_t strideElems) {
    int i = blockIdx.x * blockDim.x + threadIdx.x;
    if (i >= n4) return;
    const float4* p0 = (const float4*)p;
    const float4* p1 = (const float4*)(p + strideElems);
    const float4* p2 = (const float4*)(p + 2 * strideElems);
    const float4* p3 = (const float4*)(p + 3 * strideElems);
    float4 a = p0[i], b = p1[i], c = p2[i], d = p3[i];
    float4 r;
    r.x = a.x + b.x + c.x + d.x;
    r.y = a.y + b.y + c.y + d.y;
    r.z = a.z + b.z + c.z + d.z;
    r.w = a.w + b.w + c.w + d.w;
    ((float4*)out)[i] = r;
}

__global__ void split_z(const float* __restrict__ zcat, float* __restrict__ zm,
                        float* __restrict__ zl) {
    int i = blockIdx.x * blockDim.x + threadIdx.x;   // over NN*DCAT/4 float4s
    if (i >= NN * DCAT / 4) return;
    int row = i >> 5;          // DCAT/4 = 32 float4 per row
    int c4 = i & 31;
    float4 v = ((const float4*)zcat)[i];
    if (c4 < 16) ((float4*)zm)[(size_t)row * 16 + c4] = v;
    else         ((float4*)zl)[(size_t)row * 16 + (c4 - 16)] = v;
}

// ---------------------------------------------------------------------------
extern "C" void kernel_launch(void* const* d_in, const int* in_sizes, int n_in,
                              void* d_out, int out_size) {
    // Identify inputs by element count (robust to ordering except Wm/Wl, which
    // keep dict order): x 4,194,304 | adj 67,108,864 | W_hidden 131,072 |
    // W_mean 16,384 | W_logstd 16,384
    const float* x = nullptr;
    const float* adj = nullptr;
    const float* Wh = nullptr;
    const float* Wsmall[2] = {nullptr, nullptr};
    int nsmall = 0;
    for (int i = 0; i < n_in; i++) {
        const float* p = (const float*)d_in[i];
        switch (in_sizes[i]) {
            case NN * DIN:   x = p; break;
            case NN * NN:    adj = p; break;
            case DIN * DHID: Wh = p; break;
            case DHID * DZ:  if (nsmall < 2) Wsmall[nsmall++] = p; break;
            default: break;
        }
    }
    const float* Wm = Wsmall[0];
    const float* Wl = Wsmall[1];

    float* out = (float*)d_out;
    float* recon = out;
    float* zm = out + (size_t)NN * (size_t)NN;
    float* zl = zm + (size_t)NN * (size_t)DZ;

    float* ws = nullptr;
    cudaGetSymbolAddress((void**)&ws, g_scratch);
    float* support = ws + OFF_SUPPORT;
    float* hidden  = ws + OFF_HIDDEN;
    float* part    = ws + OFF_PART;
    float* wcat    = ws + OFF_WCAT;
    float* sbuf    = ws + OFF_S;
    float* zcat    = ws + OFF_ZCAT;

    // 1. Wcat = [W_mean | W_logstd]  (independent of the GCN chain)
    pack_w<<<(DHID * DCAT + 255) / 256, 256>>>(Wm, Wl, wcat);

    // 2. support = x @ W_hidden   [8192,512]@[512,256]
    gemm128<<<dim3(DHID / 128, NN / 128, 1), 256>>>(x, Wh, support, NN, DHID, DIN, DIN);

    // 3. hidden = relu(adj @ support)   split-K 2
    gemm128<<<dim3(DHID / 128, NN / 128, 2), 256>>>(adj, support, part, NN, DHID, NN, NN / 2);
    reduce2_relu<<<(NN * DHID / 4 + 255) / 256, 256>>>(part, part + (size_t)NN * DHID,
                                                       hidden, NN * DHID / 4);

    // 4. s = hidden @ Wcat   [8192,256]@[256,128]
    gemm128<<<dim3(DCAT / 128, NN / 128, 1), 256>>>(hidden, wcat, sbuf, NN, DCAT, DHID, DHID);

    // 5. zcat = adj @ s   split-K 4
    gemm128<<<dim3(DCAT / 128, NN / 128, 4), 256>>>(adj, sbuf, part, NN, DCAT, NN, NN / 4);
    reduce4<<<(NN * DCAT / 4 + 255) / 256, 256>>>(part, zcat, NN * DCAT / 4,
                                                  (size_t)NN * DCAT);

    // 6. split zcat -> z_mean, z_log_std (into output buffer)
    split_z<<<(NN * DCAT / 4 + 255) / 256, 256>>>(zcat, zm, zl);

    // 7. recon = z_mean @ z_mean^T (symmetric)
    recon_syrk<<<dim3(NN / 128, NN / 128), 256>>>(zm, recon);
}